// round 11
// baseline (speedup 1.0000x reference)
#include <cuda_runtime.h>
#include <math.h>
#include <stdint.h>

// ---------------- problem constants ----------------
#define T_SEQ   2048
#define C_DIM   2048
#define NH      16
#define HS      128
#define NLQ     1536
#define NLKV    512
#define DHR     64
#define DQK     (NLKV + DHR)   // 576
#define HALF_R  (DHR/2)        // 32

// ---------------- scratch (device globals; no allocation allowed) ----------------
__device__ float g_cq  [T_SEQ * (size_t)NLQ];
__device__ float g_qall[T_SEQ * (size_t)C_DIM];
__device__ float g_qr  [T_SEQ * (size_t)(NH*DHR)];
__device__ float g_kr  [T_SEQ * (size_t)DHR];
__device__ float g_krp [4 * (size_t)T_SEQ * DHR];      // kr split-K partials
__device__ float g_skp [2 * (size_t)T_SEQ * NLKV];     // shared split-K partials (steps 2,4)
__device__ float g_Qc  [(size_t)NH * T_SEQ * DQK];
__device__ float g_Kc  [(size_t)T_SEQ * DQK];
__device__ float g_S   [(size_t)NH * T_SEQ * T_SEQ];
__device__ float g_ylat[(size_t)NH * T_SEQ * NLKV];
__device__ float g_WuvT[(size_t)NLKV * C_DIM];
__device__ float g_Veff[(size_t)NLKV * C_DIM];
// tf32-rounded copies of harness inputs
__device__ float g_rx  [(size_t)T_SEQ * C_DIM];
__device__ float g_rWdq [(size_t)NLQ * C_DIM];
__device__ float g_rWuq [(size_t)NLQ * C_DIM];
__device__ float g_rWdkv[(size_t)NLKV * C_DIM];
__device__ float g_rWuk [(size_t)C_DIM * NLKV];
__device__ float g_rWqr [(size_t)(NH*DHR) * NLQ];
__device__ float g_rWkr [(size_t)DHR * C_DIM];
__device__ float g_rWo  [(size_t)C_DIM * C_DIM];

// ---------------- tf32 helpers ----------------
__device__ __forceinline__ uint32_t f2tf(float f)
{
    uint32_t r;
    asm("cvt.rna.tf32.f32 %0, %1;" : "=r"(r) : "f"(f));
    return r;
}
__device__ __forceinline__ float roundtf(float f) { return __uint_as_float(f2tf(f)); }

__device__ __forceinline__ void mma_tf32(float* d, const uint32_t* a, const uint32_t* b)
{
    asm volatile(
        "mma.sync.aligned.m16n8k8.row.col.f32.tf32.tf32.f32 "
        "{%0,%1,%2,%3},{%4,%5,%6,%7},{%8,%9},{%0,%1,%2,%3};"
        : "+f"(d[0]), "+f"(d[1]), "+f"(d[2]), "+f"(d[3])
        : "r"(a[0]), "r"(a[1]), "r"(a[2]), "r"(a[3]),
          "r"(b[0]), "r"(b[1]));
}

__device__ __forceinline__ void cp16(uint32_t dst, const void* src, bool pred)
{
    int sz = pred ? 16 : 0;
    asm volatile("cp.async.cg.shared.global [%0], [%1], 16, %2;"
                 :: "r"(dst), "l"(src), "r"(sz));
}
__device__ __forceinline__ uint32_t smaddr(const void* p)
{
    return (uint32_t)__cvta_generic_to_shared(p);
}

// ---------------- tensor-core GEMM: cp.async 3-stage, BK=32 ----------------
// CTA 128x128, 256 threads / 8 warps, warp tile 64x32 (verified mapping).
// Operands MUST be tf32-pre-rounded fp32 in gmem.
// C[m,n] = alpha * sum_k A[m,k]*B(k,n); B: BT ? B[n*ldb+k] : B[k*ldb+n].
// CMODE: 0 plain; 1 causal CTA-tile skip; 2 causal K-limit (kEnd=m0+BM).
// RND: round stored result to tf32 (for buffers consumed by later GEMMs).
// Invariants: M%128==0, kEnd%32==0, N%16==0, rows 16B-aligned.
#define BM 128
#define BN 128
#define BK 32
#define AST 36            // A (and BT-B) row stride in words: 32 + 4 pad
// per-stage words: A 128*36=4608, B max(128*36, 32*136)=4608
#define STAGE_W 9216
#define SMEM_BYTES (3 * STAGE_W * 4)

template<bool BT, int CMODE, bool RND>
__global__ __launch_bounds__(256, 2)
void gemm_tc(int M, int N, int K,
             const float* __restrict__ A, int lda, long long sA,
             const float* __restrict__ B, int ldb, long long sB,
             float* __restrict__ C, int ldc, long long sC,
             float alpha)
{
    const int m0 = blockIdx.y * BM;
    const int n0 = blockIdx.x * BN;
    if (CMODE == 1 && n0 > m0) return;
    int kEnd = K;
    if (CMODE == 2) kEnd = min(K, m0 + BM);

    const long long z = blockIdx.z;
    A += z * sA;  B += z * sB;  C += z * sC;

    extern __shared__ uint32_t dsm[];

    const int tid  = threadIdx.x;
    const int lane = tid & 31;
    const int w    = tid >> 5;
    const int gid  = lane >> 2;   // 0..7
    const int tg   = lane & 3;    // 0..3
    const int mBase = (w >> 2) * 64;
    const int nBase = (w & 3) * 32;

    // cp.async mapping: per thread 4x16B for A, 4x16B for B
    const int aRow = tid >> 1;            // 0..127
    const int aJ   = (tid & 1) * 16;      // 0 or 16
    const int bK   = tid >> 3;            // 0..31 (NN)
    const int bN4  = (tid & 7) * 16;      // 0..112 (NN)

    float acc[4][4][4];
#pragma unroll
    for (int i = 0; i < 4; i++)
#pragma unroll
        for (int j = 0; j < 4; j++)
#pragma unroll
            for (int r = 0; r < 4; r++) acc[i][j][r] = 0.f;

    auto cp_tile = [&](int s, int k0) {
        uint32_t* as = dsm + s * STAGE_W;
        uint32_t* bs = as + 4608;
        const float* pA = A + (long long)(m0 + aRow) * lda + k0 + aJ;
        uint32_t da = smaddr(&as[aRow * AST + aJ]);
#pragma unroll
        for (int j = 0; j < 4; j++)
            cp16(da + j * 16, pA + j * 4, true);
        if (BT) {
            const int gn = n0 + aRow;
            const bool p = gn < N;
            const float* pB = B + (long long)(p ? gn : 0) * ldb + k0 + aJ;
            uint32_t db = smaddr(&bs[aRow * AST + aJ]);
#pragma unroll
            for (int j = 0; j < 4; j++)
                cp16(db + j * 16, pB + j * 4, p);
        } else {
            const int gn = n0 + bN4;
            const bool p = gn < N;
            const float* pB = B + (long long)(k0 + bK) * ldb + (p ? gn : 0);
            uint32_t db = smaddr(&bs[bK * 136 + bN4]);
#pragma unroll
            for (int j = 0; j < 4; j++)
                cp16(db + j * 16, pB + j * 4, p);
        }
    };

    auto compute = [&](int s) {
        const uint32_t* as = dsm + s * STAGE_W;
        const uint32_t* bs = as + 4608;
#pragma unroll
        for (int kk = 0; kk < BK; kk += 8) {
            uint32_t af[4][4], bf[4][2];
#pragma unroll
            for (int mt = 0; mt < 4; mt++) {
                const int r = mBase + mt * 16;
                af[mt][0] = as[(r + gid) * AST + kk + tg];
                af[mt][1] = as[(r + gid + 8) * AST + kk + tg];
                af[mt][2] = as[(r + gid) * AST + kk + tg + 4];
                af[mt][3] = as[(r + gid + 8) * AST + kk + tg + 4];
            }
#pragma unroll
            for (int nt = 0; nt < 4; nt++) {
                const int c = nBase + nt * 8 + gid;
                if (BT) {
                    bf[nt][0] = bs[c * AST + kk + tg];
                    bf[nt][1] = bs[c * AST + kk + tg + 4];
                } else {
                    bf[nt][0] = bs[(kk + tg) * 136 + c];
                    bf[nt][1] = bs[(kk + tg + 4) * 136 + c];
                }
            }
#pragma unroll
            for (int mt = 0; mt < 4; mt++)
#pragma unroll
                for (int nt = 0; nt < 4; nt++)
                    mma_tf32(acc[mt][nt], af[mt], bf[nt]);
        }
    };

    const int ntiles = kEnd / BK;

    // preload 2 stages
#pragma unroll
    for (int s = 0; s < 2; s++) {
        if (s < ntiles) cp_tile(s, s * BK);
        asm volatile("cp.async.commit_group;");
    }

    for (int kt = 0; kt < ntiles; kt++) {
        asm volatile("cp.async.wait_group 1;");   // tile kt resident
        __syncthreads();                          // all warps done with stage (kt+2)%3
        const int tn = kt + 2;
        if (tn < ntiles) cp_tile(tn % 3, tn * BK);
        asm volatile("cp.async.commit_group;");
        compute(kt % 3);
    }
    asm volatile("cp.async.wait_all;");

    // epilogue
#pragma unroll
    for (int mt = 0; mt < 4; mt++) {
        const int r = m0 + mBase + mt * 16 + gid;
#pragma unroll
        for (int nt = 0; nt < 4; nt++) {
            const int c = n0 + nBase + nt * 8 + 2 * tg;
            if (c < N) {
                float2 v0, v1;
                if (RND) {
                    v0.x = roundtf(acc[mt][nt][0] * alpha);
                    v0.y = roundtf(acc[mt][nt][1] * alpha);
                    v1.x = roundtf(acc[mt][nt][2] * alpha);
                    v1.y = roundtf(acc[mt][nt][3] * alpha);
                } else {
                    v0.x = acc[mt][nt][0] * alpha;
                    v0.y = acc[mt][nt][1] * alpha;
                    v1.x = acc[mt][nt][2] * alpha;
                    v1.y = acc[mt][nt][3] * alpha;
                }
                *reinterpret_cast<float2*>(C + (long long)r * ldc + c)       = v0;
                *reinterpret_cast<float2*>(C + (long long)(r + 8) * ldc + c) = v1;
            }
        }
    }
}

// ---------------- tf32 round-copy (vectorized) ----------------
__global__ void round_copy4(const float4* __restrict__ src, float4* __restrict__ dst, int n4)
{
    int i = blockIdx.x * blockDim.x + threadIdx.x;
    if (i < n4) {
        float4 v = src[i];
        v.x = roundtf(v.x); v.y = roundtf(v.y); v.z = roundtf(v.z); v.w = roundtf(v.w);
        dst[i] = v;
    }
}

// ---------------- W_uv transpose (rounded): (2048x512) -> (512x2048) ----------------
__global__ void transpose_wuv_kernel(const float* __restrict__ W, float* __restrict__ Wt)
{
    int idx = blockIdx.x * blockDim.x + threadIdx.x;
    if (idx < C_DIM * NLKV) {
        int k = idx % NLKV;
        int c = idx / NLKV;
        Wt[(long long)k * C_DIM + c] = roundtf(W[idx]);
    }
}

// ---------------- kr split-K reduction (unrounded; rope rounds) ----------------
__global__ void reduce_kr_kernel(const float* __restrict__ krp, float* __restrict__ kr)
{
    int i = blockIdx.x * blockDim.x + threadIdx.x;
    const int n = T_SEQ * DHR;
    if (i < n)
        kr[i] = krp[i] + krp[n + i] + krp[2 * n + i] + krp[3 * n + i];
}

// ---------------- generic 2-way split-K reduce, rounded, strided dst ----------------
__global__ void reduce2_kernel(const float* __restrict__ p, float* __restrict__ dst,
                               int rows, int cols, int ldc)
{
    int i = blockIdx.x * blockDim.x + threadIdx.x;
    const int n = rows * cols;
    if (i < n) {
        int r = i / cols, c = i % cols;
        dst[(long long)r * ldc + c] = roundtf(p[i] + p[n + i]);
    }
}

// ---------------- RoPE assembly (rounded outputs) ----------------
__global__ void rope_kernel(const float* __restrict__ qr, const float* __restrict__ kr,
                            const float* __restrict__ cosT, const float* __restrict__ sinT,
                            float* __restrict__ Qc, float* __restrict__ Kc)
{
    int idx = blockIdx.x * blockDim.x + threadIdx.x;
    const int totalQ = T_SEQ * NH * HALF_R;
    if (idx < totalQ) {
        int j = idx % HALF_R;
        int h = (idx / HALF_R) % NH;
        int t = idx / (HALF_R * NH);
        float re = qr[(long long)t * (NH * DHR) + h * DHR + 2 * j];
        float im = qr[(long long)t * (NH * DHR) + h * DHR + 2 * j + 1];
        float c = cosT[t * HALF_R + j];
        float s = sinT[t * HALF_R + j];
        float* dst = Qc + ((long long)h * T_SEQ + t) * DQK + NLKV;
        dst[2 * j]     = roundtf(re * c - im * s);
        dst[2 * j + 1] = roundtf(re * s + im * c);
    } else {
        int k = idx - totalQ;
        if (k < T_SEQ * HALF_R) {
            int j = k % HALF_R;
            int t = k / HALF_R;
            float re = kr[t * DHR + 2 * j];
            float im = kr[t * DHR + 2 * j + 1];
            float c = cosT[t * HALF_R + j];
            float s = sinT[t * HALF_R + j];
            Kc[(long long)t * DQK + NLKV + 2 * j]     = roundtf(re * c - im * s);
            Kc[(long long)t * DQK + NLKV + 2 * j + 1] = roundtf(re * s + im * c);
        }
    }
}

// ---------------- causal softmax (rounded probs; zero-fill only to 128-boundary) ----------------
__global__ __launch_bounds__(256)
void softmax_kernel(float* __restrict__ S)
{
    const int t = blockIdx.x;
    float* row = S + ((long long)blockIdx.y * T_SEQ + t) * (long long)T_SEQ;
    const int len = t + 1;
    const int tid = threadIdx.x;
    __shared__ float sm[32];

    float m = -3.4e38f;
    for (int i = tid; i < len; i += 256) m = fmaxf(m, row[i]);
#pragma unroll
    for (int o = 16; o; o >>= 1) m = fmaxf(m, __shfl_xor_sync(0xffffffffu, m, o));
    if ((tid & 31) == 0) sm[tid >> 5] = m;
    __syncthreads();
    if (tid < 32) {
        float v = (tid < 8) ? sm[tid] : -3.4e38f;
#pragma unroll
        for (int o = 4; o; o >>= 1) v = fmaxf(v, __shfl_xor_sync(0xffffffffu, v, o));
        if (tid == 0) sm[0] = v;
    }
    __syncthreads();
    m = sm[0];
    __syncthreads();

    float s = 0.f;
    for (int i = tid; i < len; i += 256) {
        float e = expf(row[i] - m);
        row[i] = e;
        s += e;
    }
#pragma unroll
    for (int o = 16; o; o >>= 1) s += __shfl_xor_sync(0xffffffffu, s, o);
    if ((tid & 31) == 0) sm[tid >> 5] = s;
    __syncthreads();
    if (tid < 32) {
        float v = (tid < 8) ? sm[tid] : 0.f;
#pragma unroll
        for (int o = 4; o; o >>= 1) v += __shfl_xor_sync(0xffffffffu, v, o);
        if (tid == 0) sm[0] = v;
    }
    __syncthreads();
    const float inv = 1.f / sm[0];
    for (int i = tid; i < len; i += 256) row[i] = roundtf(row[i] * inv);
    // PV GEMM reads cols < round_up(len,128) only — fill just that window.
    const int fillEnd = min(T_SEQ, (len + 127) & ~127);
    for (int i = len + tid; i < fillEnd; i += 256) row[i] = 0.f;
}

// ---------------- host orchestration ----------------
static inline dim3 gemm_grid(int M, int N, int Z)
{
    return dim3((N + BN - 1) / BN, (M + BM - 1) / BM, Z);
}

static void rcopy(const float* src, float* dst, int n)
{
    int n4 = n / 4;
    round_copy4<<<(n4 + 255) / 256, 256>>>((const float4*)src, (float4*)dst, n4);
}

extern "C" void kernel_launch(void* const* d_in, const int* in_sizes, int n_in,
                              void* d_out, int out_size)
{
    const float* x     = (const float*)d_in[0];
    const float* fcos  = (const float*)d_in[1];
    const float* fsin  = (const float*)d_in[2];
    const float* W_dq  = (const float*)d_in[3];
    const float* W_uq  = (const float*)d_in[4];
    const float* W_dkv = (const float*)d_in[5];
    const float* W_uk  = (const float*)d_in[6];
    const float* W_uv  = (const float*)d_in[7];
    const float* W_qr  = (const float*)d_in[8];
    const float* W_kr  = (const float*)d_in[9];
    const float* W_o   = (const float*)d_in[10];
    float* out = (float*)d_out;

    float *p_cq, *p_qall, *p_qr, *p_kr, *p_krp, *p_skp, *p_Qc, *p_Kc, *p_S, *p_ylat, *p_WuvT, *p_Veff;
    float *p_rx, *p_rWdq, *p_rWuq, *p_rWdkv, *p_rWuk, *p_rWqr, *p_rWkr, *p_rWo;
    cudaGetSymbolAddress((void**)&p_cq,   g_cq);
    cudaGetSymbolAddress((void**)&p_qall, g_qall);
    cudaGetSymbolAddress((void**)&p_qr,   g_qr);
    cudaGetSymbolAddress((void**)&p_kr,   g_kr);
    cudaGetSymbolAddress((void**)&p_krp,  g_krp);
    cudaGetSymbolAddress((void**)&p_skp,  g_skp);
    cudaGetSymbolAddress((void**)&p_Qc,   g_Qc);
    cudaGetSymbolAddress((void**)&p_Kc,   g_Kc);
    cudaGetSymbolAddress((void**)&p_S,    g_S);
    cudaGetSymbolAddress((void**)&p_ylat, g_ylat);
    cudaGetSymbolAddress((void**)&p_WuvT, g_WuvT);
    cudaGetSymbolAddress((void**)&p_Veff, g_Veff);
    cudaGetSymbolAddress((void**)&p_rx,   g_rx);
    cudaGetSymbolAddress((void**)&p_rWdq, g_rWdq);
    cudaGetSymbolAddress((void**)&p_rWuq, g_rWuq);
    cudaGetSymbolAddress((void**)&p_rWdkv,g_rWdkv);
    cudaGetSymbolAddress((void**)&p_rWuk, g_rWuk);
    cudaGetSymbolAddress((void**)&p_rWqr, g_rWqr);
    cudaGetSymbolAddress((void**)&p_rWkr, g_rWkr);
    cudaGetSymbolAddress((void**)&p_rWo,  g_rWo);

    cudaFuncSetAttribute(gemm_tc<true, 0, true>,  cudaFuncAttributeMaxDynamicSharedMemorySize, SMEM_BYTES);
    cudaFuncSetAttribute(gemm_tc<true, 0, false>, cudaFuncAttributeMaxDynamicSharedMemorySize, SMEM_BYTES);
    cudaFuncSetAttribute(gemm_tc<true, 1, false>, cudaFuncAttributeMaxDynamicSharedMemorySize, SMEM_BYTES);
    cudaFuncSetAttribute(gemm_tc<false, 0, true>, cudaFuncAttributeMaxDynamicSharedMemorySize, SMEM_BYTES);
    cudaFuncSetAttribute(gemm_tc<false, 0, false>,cudaFuncAttributeMaxDynamicSharedMemorySize, SMEM_BYTES);
    cudaFuncSetAttribute(gemm_tc<false, 2, true>, cudaFuncAttributeMaxDynamicSharedMemorySize, SMEM_BYTES);

    const float scale = 1.0f / sqrtf((float)(HS + DHR));
    const dim3 blk(256);

    // 0) tf32 round-copies of GEMM operands
    rcopy(x,     p_rx,   T_SEQ * C_DIM);
    rcopy(W_dq,  p_rWdq, NLQ * C_DIM);
    rcopy(W_uq,  p_rWuq, NLQ * C_DIM);
    rcopy(W_dkv, p_rWdkv,NLKV * C_DIM);
    rcopy(W_uk,  p_rWuk, C_DIM * NLKV);
    rcopy(W_qr,  p_rWqr, NH * DHR * NLQ);
    rcopy(W_kr,  p_rWkr, DHR * C_DIM);
    rcopy(W_o,   p_rWo,  C_DIM * C_DIM);
    transpose_wuv_kernel<<<(C_DIM * NLKV + 255) / 256, blk>>>(W_uv, p_WuvT);

    // 1) c_q = x @ W_dq^T              (2048x1536, K=2048)  NT, rounded
    gemm_tc<true, 0, true><<<gemm_grid(T_SEQ, NLQ, 1), blk, SMEM_BYTES>>>(
        T_SEQ, NLQ, C_DIM, p_rx, C_DIM, 0, p_rWdq, C_DIM, 0, p_cq, NLQ, 0, 1.f);

    // 2) Kc[:, 0:512] = x @ W_dkv^T    split-K x2 (K=1024 each) -> 128 CTAs
    gemm_tc<true, 0, false><<<dim3(4, 16, 2), blk, SMEM_BYTES>>>(
        T_SEQ, NLKV, 1024,
        p_rx,    C_DIM, 1024LL,
        p_rWdkv, C_DIM, 1024LL,
        p_skp,   NLKV,  (long long)T_SEQ * NLKV, 1.f);
    reduce2_kernel<<<(T_SEQ * NLKV + 255) / 256, blk>>>(p_skp, p_Kc, T_SEQ, NLKV, DQK);

    // 3) kr partials = x @ W_kr^T      split-K x4 -> 64 CTAs
    gemm_tc<true, 0, false><<<dim3(1, 16, 4), blk, SMEM_BYTES>>>(
        T_SEQ, DHR, 512,
        p_rx,   C_DIM, 512LL,
        p_rWkr, C_DIM, 512LL,
        p_krp,  DHR,   (long long)T_SEQ * DHR, 1.f);
    reduce_kr_kernel<<<(T_SEQ * DHR + 255) / 256, blk>>>(p_krp, p_kr);

    // 4) Veff = WuvT @ W_o^T           split-K x2 (K=1024 each) -> 128 CTAs
    gemm_tc<true, 0, false><<<dim3(16, 4, 2), blk, SMEM_BYTES>>>(
        NLKV, C_DIM, 1024,
        p_WuvT, C_DIM, 1024LL,
        p_rWo,  C_DIM, 1024LL,
        p_skp,  C_DIM, (long long)NLKV * C_DIM, 1.f);
    reduce2_kernel<<<(NLKV * C_DIM + 255) / 256, blk>>>(p_skp, p_Veff, NLKV, C_DIM, C_DIM);

    // 5) q_all = c_q @ M_uq            (2048x2048, K=1536)  NN, rounded
    gemm_tc<false, 0, true><<<gemm_grid(T_SEQ, C_DIM, 1), blk, SMEM_BYTES>>>(
        T_SEQ, C_DIM, NLQ, p_cq, NLQ, 0, p_rWuq, C_DIM, 0, p_qall, C_DIM, 0, 1.f);

    // 6) qr_all = c_q @ W_qr^T         (2048x1024, K=1536)  NT
    gemm_tc<true, 0, false><<<gemm_grid(T_SEQ, NH * DHR, 1), blk, SMEM_BYTES>>>(
        T_SEQ, NH * DHR, NLQ, p_cq, NLQ, 0, p_rWqr, NLQ, 0, p_qr, NH * DHR, 0, 1.f);

    // 7) Qc[h][:, 0:512] = q_all[:, h*128:] @ W_uk[h*128:, :]   batched NN, rounded
    gemm_tc<false, 0, true><<<gemm_grid(T_SEQ, NLKV, NH), blk, SMEM_BYTES>>>(
        T_SEQ, NLKV, HS,
        p_qall, C_DIM, (long long)HS,
        p_rWuk, NLKV,  (long long)HS * NLKV,
        p_Qc,   DQK,   (long long)T_SEQ * DQK, 1.f);

    // 8) RoPE -> Qc[...,512:576], Kc[...,512:576] (rounded)
    {
        int total = T_SEQ * NH * HALF_R + T_SEQ * HALF_R;
        rope_kernel<<<(total + 255) / 256, blk>>>(p_qr, p_kr, fcos, fsin, p_Qc, p_Kc);
    }

    // 9) S[h] = scale * Qc[h] @ Kc^T   (2048x2048, K=576) batched NT, causal skip
    gemm_tc<true, 1, false><<<gemm_grid(T_SEQ, T_SEQ, NH), blk, SMEM_BYTES>>>(
        T_SEQ, T_SEQ, DQK,
        p_Qc, DQK, (long long)T_SEQ * DQK,
        p_Kc, DQK, 0LL,
        p_S,  T_SEQ, (long long)T_SEQ * T_SEQ, scale);

    // 10) causal softmax (rounded probs, trimmed zero-fill)
    softmax_kernel<<<dim3(T_SEQ, NH), blk>>>(p_S);

    // 11) y_lat[h] = P[h] @ Kc[:, 0:512]   batched NN, K-limited, rounded
    gemm_tc<false, 2, true><<<gemm_grid(T_SEQ, NLKV, NH), blk, SMEM_BYTES>>>(
        T_SEQ, NLKV, T_SEQ,
        p_S,  T_SEQ, (long long)T_SEQ * T_SEQ,
        p_Kc, DQK,   0LL,
        p_ylat, NLKV, (long long)T_SEQ * NLKV, 1.f);

    // 12) out[:, h*128:(h+1)*128] = y_lat[h] @ Veff[:, h*128:]  batched NN
    gemm_tc<false, 0, false><<<gemm_grid(T_SEQ, HS, NH), blk, SMEM_BYTES>>>(
        T_SEQ, HS, NLKV,
        p_ylat, NLKV, (long long)T_SEQ * NLKV,
        p_Veff, C_DIM, (long long)HS,
        out,    C_DIM, (long long)HS, 1.f);
}

// round 12
// speedup vs baseline: 1.1235x; 1.1235x over previous
#include <cuda_runtime.h>
#include <math.h>
#include <stdint.h>

// ---------------- problem constants ----------------
#define T_SEQ   2048
#define C_DIM   2048
#define NH      16
#define HS      128
#define NLQ     1536
#define NLKV    512
#define DHR     64
#define DQK     (NLKV + DHR)   // 576
#define HALF_R  (DHR/2)        // 32

// ---------------- scratch (device globals; no allocation allowed) ----------------
__device__ float g_cq  [T_SEQ * (size_t)NLQ];
__device__ float g_qall[T_SEQ * (size_t)C_DIM];
__device__ float g_qr  [T_SEQ * (size_t)(NH*DHR)];
__device__ float g_skp [2 * (size_t)T_SEQ * DQK];      // split-K partials (steps 2,4)
__device__ float g_Qc  [(size_t)NH * T_SEQ * DQK];
__device__ float g_Kc  [(size_t)T_SEQ * DQK];
__device__ float g_S   [(size_t)NH * T_SEQ * T_SEQ];
__device__ float g_ylat[(size_t)NH * T_SEQ * NLKV];
__device__ float g_WuvT[(size_t)NLKV * C_DIM];
__device__ float g_Veff[(size_t)NLKV * C_DIM];
// tf32-rounded copies of harness inputs
__device__ float g_rx  [(size_t)T_SEQ * C_DIM];
__device__ float g_rWdq [(size_t)NLQ * C_DIM];
__device__ float g_rWuq [(size_t)NLQ * C_DIM];
__device__ float g_rWkc [(size_t)DQK * C_DIM];         // [W_dkv; W_kr] concat (576x2048)
__device__ float g_rWuk [(size_t)C_DIM * NLKV];
__device__ float g_rWqr [(size_t)(NH*DHR) * NLQ];
__device__ float g_rWo  [(size_t)C_DIM * C_DIM];

// ---------------- tf32 helpers ----------------
__device__ __forceinline__ uint32_t f2tf(float f)
{
    uint32_t r;
    asm("cvt.rna.tf32.f32 %0, %1;" : "=r"(r) : "f"(f));
    return r;
}
__device__ __forceinline__ float roundtf(float f) { return __uint_as_float(f2tf(f)); }

__device__ __forceinline__ void mma_tf32(float* d, const uint32_t* a, const uint32_t* b)
{
    asm volatile(
        "mma.sync.aligned.m16n8k8.row.col.f32.tf32.tf32.f32 "
        "{%0,%1,%2,%3},{%4,%5,%6,%7},{%8,%9},{%0,%1,%2,%3};"
        : "+f"(d[0]), "+f"(d[1]), "+f"(d[2]), "+f"(d[3])
        : "r"(a[0]), "r"(a[1]), "r"(a[2]), "r"(a[3]),
          "r"(b[0]), "r"(b[1]));
}

__device__ __forceinline__ void cp16(uint32_t dst, const void* src, bool pred)
{
    int sz = pred ? 16 : 0;
    asm volatile("cp.async.cg.shared.global [%0], [%1], 16, %2;"
                 :: "r"(dst), "l"(src), "r"(sz));
}
__device__ __forceinline__ uint32_t smaddr(const void* p)
{
    return (uint32_t)__cvta_generic_to_shared(p);
}

// ---------------- tensor-core GEMM: cp.async 4-stage pipeline (R8 engine) ----------------
// CTA 128x128, 256 threads / 8 warps, warp tile 64x32.
// Operands MUST be tf32-pre-rounded fp32 in gmem.
// C[m,n] = alpha * sum_k A[m,k]*B(k,n); B: BT ? B[n*ldb+k] : B[k*ldb+n].
// CMODE: 0 plain; 1 causal CTA-tile skip; 2 causal K-limit (kEnd=m0+BM).
// RND: round stored result to tf32.
// Invariants: M%128==0, kEnd%16==0, N%4==0, rows 16B-aligned.
#define BM 128
#define BN 128
#define BK 16
#define STAGE_W 5120
#define SMEM_BYTES (4 * STAGE_W * 4)

template<bool BT, int CMODE, bool RND>
__global__ __launch_bounds__(256, 2)
void gemm_tc(int M, int N, int K,
             const float* __restrict__ A, int lda, long long sA,
             const float* __restrict__ B, int ldb, long long sB,
             float* __restrict__ C, int ldc, long long sC,
             float alpha)
{
    const int m0 = blockIdx.y * BM;
    const int n0 = blockIdx.x * BN;
    if (CMODE == 1 && n0 > m0) return;
    int kEnd = K;
    if (CMODE == 2) kEnd = min(K, m0 + BM);

    const long long z = blockIdx.z;
    A += z * sA;  B += z * sB;  C += z * sC;

    extern __shared__ uint32_t dsm[];

    const int tid  = threadIdx.x;
    const int lane = tid & 31;
    const int w    = tid >> 5;
    const int gid  = lane >> 2;   // 0..7
    const int tg   = lane & 3;    // 0..3
    const int mBase = (w >> 2) * 64;
    const int nBase = (w & 3) * 32;

    // cp.async mapping: per thread 2x16B for A, 2x16B for B
    const int aRow = tid >> 1;            // 0..127
    const int aJ   = (tid & 1) * 8;       // 0 or 8
    const int bK   = tid >> 5;            // 0..7 (NN)
    const int bN4  = (tid & 31) * 4;      // 0..124 (NN)

    float acc[4][4][4];
#pragma unroll
    for (int i = 0; i < 4; i++)
#pragma unroll
        for (int j = 0; j < 4; j++)
#pragma unroll
            for (int r = 0; r < 4; r++) acc[i][j][r] = 0.f;

    auto cp_tile = [&](int s, int k0) {
        uint32_t* as = dsm + s * STAGE_W;
        uint32_t* bs = as + 2560;
        const float* pA = A + (long long)(m0 + aRow) * lda + k0 + aJ;
        cp16(smaddr(&as[aRow * 20 + aJ]),     pA,     true);
        cp16(smaddr(&as[aRow * 20 + aJ + 4]), pA + 4, true);
        if (BT) {
            const int gn = n0 + aRow;
            const bool p = gn < N;
            const float* pB = B + (long long)(p ? gn : 0) * ldb + k0 + aJ;
            cp16(smaddr(&bs[aRow * 20 + aJ]),     pB,     p);
            cp16(smaddr(&bs[aRow * 20 + aJ + 4]), pB + 4, p);
        } else {
            const int gn = n0 + bN4;
            const bool p = gn < N;
            const int gc = p ? gn : 0;
            cp16(smaddr(&bs[bK * 136 + bN4]),       B + (long long)(k0 + bK) * ldb + gc,     p);
            cp16(smaddr(&bs[(bK + 8) * 136 + bN4]), B + (long long)(k0 + bK + 8) * ldb + gc, p);
        }
    };

    auto compute = [&](int s) {
        const uint32_t* as = dsm + s * STAGE_W;
        const uint32_t* bs = as + 2560;
#pragma unroll
        for (int kk = 0; kk < BK; kk += 8) {
            uint32_t af[4][4], bf[4][2];
#pragma unroll
            for (int mt = 0; mt < 4; mt++) {
                const int r = mBase + mt * 16;
                af[mt][0] = as[(r + gid) * 20 + kk + tg];
                af[mt][1] = as[(r + gid + 8) * 20 + kk + tg];
                af[mt][2] = as[(r + gid) * 20 + kk + tg + 4];
                af[mt][3] = as[(r + gid + 8) * 20 + kk + tg + 4];
            }
#pragma unroll
            for (int nt = 0; nt < 4; nt++) {
                const int c = nBase + nt * 8 + gid;
                if (BT) {
                    bf[nt][0] = bs[c * 20 + kk + tg];
                    bf[nt][1] = bs[c * 20 + kk + tg + 4];
                } else {
                    bf[nt][0] = bs[(kk + tg) * 136 + c];
                    bf[nt][1] = bs[(kk + tg + 4) * 136 + c];
                }
            }
#pragma unroll
            for (int mt = 0; mt < 4; mt++)
#pragma unroll
                for (int nt = 0; nt < 4; nt++)
                    mma_tf32(acc[mt][nt], af[mt], bf[nt]);
        }
    };

    const int ntiles = kEnd / BK;

#pragma unroll
    for (int s = 0; s < 3; s++) {
        if (s < ntiles) cp_tile(s, s * BK);
        asm volatile("cp.async.commit_group;");
    }

    for (int kt = 0; kt < ntiles; kt++) {
        asm volatile("cp.async.wait_group 2;");
        __syncthreads();
        const int tn = kt + 3;
        if (tn < ntiles) cp_tile(tn & 3, tn * BK);
        asm volatile("cp.async.commit_group;");
        compute(kt & 3);
    }
    asm volatile("cp.async.wait_all;");

    // epilogue
#pragma unroll
    for (int mt = 0; mt < 4; mt++) {
        const int r = m0 + mBase + mt * 16 + gid;
#pragma unroll
        for (int nt = 0; nt < 4; nt++) {
            const int c = n0 + nBase + nt * 8 + 2 * tg;
            if (c < N) {
                float2 v0, v1;
                if (RND) {
                    v0.x = roundtf(acc[mt][nt][0] * alpha);
                    v0.y = roundtf(acc[mt][nt][1] * alpha);
                    v1.x = roundtf(acc[mt][nt][2] * alpha);
                    v1.y = roundtf(acc[mt][nt][3] * alpha);
                } else {
                    v0.x = acc[mt][nt][0] * alpha;
                    v0.y = acc[mt][nt][1] * alpha;
                    v1.x = acc[mt][nt][2] * alpha;
                    v1.y = acc[mt][nt][3] * alpha;
                }
                *reinterpret_cast<float2*>(C + (long long)r * ldc + c)       = v0;
                *reinterpret_cast<float2*>(C + (long long)(r + 8) * ldc + c) = v1;
            }
        }
    }
}

// ---------------- tf32 round-copy (vectorized) ----------------
__global__ void round_copy4(const float4* __restrict__ src, float4* __restrict__ dst, int n4)
{
    int i = blockIdx.x * blockDim.x + threadIdx.x;
    if (i < n4) {
        float4 v = src[i];
        v.x = roundtf(v.x); v.y = roundtf(v.y); v.z = roundtf(v.z); v.w = roundtf(v.w);
        dst[i] = v;
    }
}

// ---------------- W_uv transpose (rounded): (2048x512) -> (512x2048) ----------------
__global__ void transpose_wuv_kernel(const float* __restrict__ W, float* __restrict__ Wt)
{
    int idx = blockIdx.x * blockDim.x + threadIdx.x;
    if (idx < C_DIM * NLKV) {
        int k = idx % NLKV;
        int c = idx / NLKV;
        Wt[(long long)k * C_DIM + c] = roundtf(W[idx]);
    }
}

// ---------------- 2-way split-K reduce, rounded, strided dst ----------------
__global__ void reduce2_kernel(const float* __restrict__ p, float* __restrict__ dst,
                               int rows, int cols, int ldc, long long sp)
{
    int i = blockIdx.x * blockDim.x + threadIdx.x;
    const int n = rows * cols;
    if (i < n) {
        int r = i / cols, c = i % cols;
        dst[(long long)r * ldc + c] = roundtf(p[i] + p[sp + i]);
    }
}

// ---------------- RoPE assembly (Q from g_qr; K in place on Kc cols 512:576) ----------------
__global__ void rope_kernel(const float* __restrict__ qr,
                            const float* __restrict__ cosT, const float* __restrict__ sinT,
                            float* __restrict__ Qc, float* __restrict__ Kc)
{
    int idx = blockIdx.x * blockDim.x + threadIdx.x;
    const int totalQ = T_SEQ * NH * HALF_R;
    if (idx < totalQ) {
        int j = idx % HALF_R;
        int h = (idx / HALF_R) % NH;
        int t = idx / (HALF_R * NH);
        float re = qr[(long long)t * (NH * DHR) + h * DHR + 2 * j];
        float im = qr[(long long)t * (NH * DHR) + h * DHR + 2 * j + 1];
        float c = cosT[t * HALF_R + j];
        float s = sinT[t * HALF_R + j];
        float* dst = Qc + ((long long)h * T_SEQ + t) * DQK + NLKV;
        dst[2 * j]     = roundtf(re * c - im * s);
        dst[2 * j + 1] = roundtf(re * s + im * c);
    } else {
        int k = idx - totalQ;
        if (k < T_SEQ * HALF_R) {
            int j = k % HALF_R;
            int t = k / HALF_R;
            float* kp = Kc + (long long)t * DQK + NLKV;
            float re = kp[2 * j];
            float im = kp[2 * j + 1];
            float c = cosT[t * HALF_R + j];
            float s = sinT[t * HALF_R + j];
            kp[2 * j]     = roundtf(re * c - im * s);
            kp[2 * j + 1] = roundtf(re * s + im * c);
        }
    }
}

// ---------------- causal softmax (rounded probs; zero-fill to 128-boundary only) ----------------
__global__ __launch_bounds__(256)
void softmax_kernel(float* __restrict__ S)
{
    const int t = blockIdx.x;
    float* row = S + ((long long)blockIdx.y * T_SEQ + t) * (long long)T_SEQ;
    const int len = t + 1;
    const int tid = threadIdx.x;
    __shared__ float sm[32];

    float m = -3.4e38f;
    for (int i = tid; i < len; i += 256) m = fmaxf(m, row[i]);
#pragma unroll
    for (int o = 16; o; o >>= 1) m = fmaxf(m, __shfl_xor_sync(0xffffffffu, m, o));
    if ((tid & 31) == 0) sm[tid >> 5] = m;
    __syncthreads();
    if (tid < 32) {
        float v = (tid < 8) ? sm[tid] : -3.4e38f;
#pragma unroll
        for (int o = 4; o; o >>= 1) v = fmaxf(v, __shfl_xor_sync(0xffffffffu, v, o));
        if (tid == 0) sm[0] = v;
    }
    __syncthreads();
    m = sm[0];
    __syncthreads();

    float s = 0.f;
    for (int i = tid; i < len; i += 256) {
        float e = expf(row[i] - m);
        row[i] = e;
        s += e;
    }
#pragma unroll
    for (int o = 16; o; o >>= 1) s += __shfl_xor_sync(0xffffffffu, s, o);
    if ((tid & 31) == 0) sm[tid >> 5] = s;
    __syncthreads();
    if (tid < 32) {
        float v = (tid < 8) ? sm[tid] : 0.f;
#pragma unroll
        for (int o = 4; o; o >>= 1) v += __shfl_xor_sync(0xffffffffu, v, o);
        if (tid == 0) sm[0] = v;
    }
    __syncthreads();
    const float inv = 1.f / sm[0];
    for (int i = tid; i < len; i += 256) row[i] = roundtf(row[i] * inv);
    const int fillEnd = min(T_SEQ, (len + 127) & ~127);   // PV GEMM reads only this window
    for (int i = len + tid; i < fillEnd; i += 256) row[i] = 0.f;
}

// ---------------- host orchestration ----------------
static inline dim3 gemm_grid(int M, int N, int Z)
{
    return dim3((N + BN - 1) / BN, (M + BM - 1) / BM, Z);
}

static void rcopy(const float* src, float* dst, int n)
{
    int n4 = n / 4;
    round_copy4<<<(n4 + 255) / 256, 256>>>((const float4*)src, (float4*)dst, n4);
}

extern "C" void kernel_launch(void* const* d_in, const int* in_sizes, int n_in,
                              void* d_out, int out_size)
{
    const float* x     = (const float*)d_in[0];
    const float* fcos  = (const float*)d_in[1];
    const float* fsin  = (const float*)d_in[2];
    const float* W_dq  = (const float*)d_in[3];
    const float* W_uq  = (const float*)d_in[4];
    const float* W_dkv = (const float*)d_in[5];
    const float* W_uk  = (const float*)d_in[6];
    const float* W_uv  = (const float*)d_in[7];
    const float* W_qr  = (const float*)d_in[8];
    const float* W_kr  = (const float*)d_in[9];
    const float* W_o   = (const float*)d_in[10];
    float* out = (float*)d_out;

    float *p_cq, *p_qall, *p_qr, *p_skp, *p_Qc, *p_Kc, *p_S, *p_ylat, *p_WuvT, *p_Veff;
    float *p_rx, *p_rWdq, *p_rWuq, *p_rWkc, *p_rWuk, *p_rWqr, *p_rWo;
    cudaGetSymbolAddress((void**)&p_cq,   g_cq);
    cudaGetSymbolAddress((void**)&p_qall, g_qall);
    cudaGetSymbolAddress((void**)&p_qr,   g_qr);
    cudaGetSymbolAddress((void**)&p_skp,  g_skp);
    cudaGetSymbolAddress((void**)&p_Qc,   g_Qc);
    cudaGetSymbolAddress((void**)&p_Kc,   g_Kc);
    cudaGetSymbolAddress((void**)&p_S,    g_S);
    cudaGetSymbolAddress((void**)&p_ylat, g_ylat);
    cudaGetSymbolAddress((void**)&p_WuvT, g_WuvT);
    cudaGetSymbolAddress((void**)&p_Veff, g_Veff);
    cudaGetSymbolAddress((void**)&p_rx,   g_rx);
    cudaGetSymbolAddress((void**)&p_rWdq, g_rWdq);
    cudaGetSymbolAddress((void**)&p_rWuq, g_rWuq);
    cudaGetSymbolAddress((void**)&p_rWkc, g_rWkc);
    cudaGetSymbolAddress((void**)&p_rWuk, g_rWuk);
    cudaGetSymbolAddress((void**)&p_rWqr, g_rWqr);
    cudaGetSymbolAddress((void**)&p_rWo,  g_rWo);

    cudaFuncSetAttribute(gemm_tc<true, 0, true>,  cudaFuncAttributeMaxDynamicSharedMemorySize, SMEM_BYTES);
    cudaFuncSetAttribute(gemm_tc<true, 0, false>, cudaFuncAttributeMaxDynamicSharedMemorySize, SMEM_BYTES);
    cudaFuncSetAttribute(gemm_tc<true, 1, false>, cudaFuncAttributeMaxDynamicSharedMemorySize, SMEM_BYTES);
    cudaFuncSetAttribute(gemm_tc<false, 0, true>, cudaFuncAttributeMaxDynamicSharedMemorySize, SMEM_BYTES);
    cudaFuncSetAttribute(gemm_tc<false, 0, false>,cudaFuncAttributeMaxDynamicSharedMemorySize, SMEM_BYTES);
    cudaFuncSetAttribute(gemm_tc<false, 2, true>, cudaFuncAttributeMaxDynamicSharedMemorySize, SMEM_BYTES);

    const float scale = 1.0f / sqrtf((float)(HS + DHR));
    const dim3 blk(256);

    // 0) tf32 round-copies (W_dkv and W_kr concatenated into one 576x2048 weight)
    rcopy(x,     p_rx,   T_SEQ * C_DIM);
    rcopy(W_dq,  p_rWdq, NLQ * C_DIM);
    rcopy(W_uq,  p_rWuq, NLQ * C_DIM);
    rcopy(W_dkv, p_rWkc, NLKV * C_DIM);
    rcopy(W_kr,  p_rWkc + (size_t)NLKV * C_DIM, DHR * C_DIM);
    rcopy(W_uk,  p_rWuk, C_DIM * NLKV);
    rcopy(W_qr,  p_rWqr, NH * DHR * NLQ);
    rcopy(W_o,   p_rWo,  C_DIM * C_DIM);
    transpose_wuv_kernel<<<(C_DIM * NLKV + 255) / 256, blk>>>(W_uv, p_WuvT);

    // 1) c_q = x @ W_dq^T              (2048x1536, K=2048)  NT, rounded
    gemm_tc<true, 0, true><<<gemm_grid(T_SEQ, NLQ, 1), blk, SMEM_BYTES>>>(
        T_SEQ, NLQ, C_DIM, p_rx, C_DIM, 0, p_rWdq, C_DIM, 0, p_cq, NLQ, 0, 1.f);

    // 2) Kc (all 576 cols) = x @ [W_dkv;W_kr]^T   split-K x2 -> 160 CTAs + reduce
    gemm_tc<true, 0, false><<<dim3(5, 16, 2), blk, SMEM_BYTES>>>(
        T_SEQ, DQK, 1024,
        p_rx,   C_DIM, 1024LL,
        p_rWkc, C_DIM, 1024LL,
        p_skp,  DQK,   (long long)T_SEQ * DQK, 1.f);
    reduce2_kernel<<<(T_SEQ * DQK + 255) / 256, blk>>>(
        p_skp, p_Kc, T_SEQ, DQK, DQK, (long long)T_SEQ * DQK);

    // 4) Veff = WuvT @ W_o^T           split-K x2 -> 128 CTAs + reduce
    gemm_tc<true, 0, false><<<dim3(16, 4, 2), blk, SMEM_BYTES>>>(
        NLKV, C_DIM, 1024,
        p_WuvT, C_DIM, 1024LL,
        p_rWo,  C_DIM, 1024LL,
        p_skp,  C_DIM, (long long)NLKV * C_DIM, 1.f);
    reduce2_kernel<<<(NLKV * C_DIM + 255) / 256, blk>>>(
        p_skp, p_Veff, NLKV, C_DIM, C_DIM, (long long)NLKV * C_DIM);

    // 5) q_all = c_q @ M_uq            (2048x2048, K=1536)  NN, rounded
    gemm_tc<false, 0, true><<<gemm_grid(T_SEQ, C_DIM, 1), blk, SMEM_BYTES>>>(
        T_SEQ, C_DIM, NLQ, p_cq, NLQ, 0, p_rWuq, C_DIM, 0, p_qall, C_DIM, 0, 1.f);

    // 6) qr_all = c_q @ W_qr^T         (2048x1024, K=1536)  NT
    gemm_tc<true, 0, false><<<gemm_grid(T_SEQ, NH * DHR, 1), blk, SMEM_BYTES>>>(
        T_SEQ, NH * DHR, NLQ, p_cq, NLQ, 0, p_rWqr, NLQ, 0, p_qr, NH * DHR, 0, 1.f);

    // 7) Qc[h][:, 0:512] = q_all[:, h*128:] @ W_uk[h*128:, :]   batched NN, rounded
    gemm_tc<false, 0, true><<<gemm_grid(T_SEQ, NLKV, NH), blk, SMEM_BYTES>>>(
        T_SEQ, NLKV, HS,
        p_qall, C_DIM, (long long)HS,
        p_rWuk, NLKV,  (long long)HS * NLKV,
        p_Qc,   DQK,   (long long)T_SEQ * DQK, 1.f);

    // 8) RoPE: Qc[...,512:576] from qr_all; Kc[...,512:576] in place
    {
        int total = T_SEQ * NH * HALF_R + T_SEQ * HALF_R;
        rope_kernel<<<(total + 255) / 256, blk>>>(p_qr, fcos, fsin, p_Qc, p_Kc);
    }

    // 9) S[h] = scale * Qc[h] @ Kc^T   (2048x2048, K=576) batched NT, causal skip
    gemm_tc<true, 1, false><<<gemm_grid(T_SEQ, T_SEQ, NH), blk, SMEM_BYTES>>>(
        T_SEQ, T_SEQ, DQK,
        p_Qc, DQK, (long long)T_SEQ * DQK,
        p_Kc, DQK, 0LL,
        p_S,  T_SEQ, (long long)T_SEQ * T_SEQ, scale);

    // 10) causal softmax (rounded probs, trimmed zero-fill)
    softmax_kernel<<<dim3(T_SEQ, NH), blk>>>(p_S);

    // 11) y_lat[h] = P[h] @ Kc[:, 0:512]   batched NN, K-limited, rounded
    gemm_tc<false, 2, true><<<gemm_grid(T_SEQ, NLKV, NH), blk, SMEM_BYTES>>>(
        T_SEQ, NLKV, T_SEQ,
        p_S,  T_SEQ, (long long)T_SEQ * T_SEQ,
        p_Kc, DQK,   0LL,
        p_ylat, NLKV, (long long)T_SEQ * NLKV, 1.f);

    // 12) out[:, h*128:(h+1)*128] = y_lat[h] @ Veff[:, h*128:]  batched NN
    gemm_tc<false, 0, false><<<gemm_grid(T_SEQ, HS, NH), blk, SMEM_BYTES>>>(
        T_SEQ, HS, NLKV,
        p_ylat, NLKV, (long long)T_SEQ * NLKV,
        p_Veff, C_DIM, (long long)HS,
        out,    C_DIM, (long long)HS, 1.f);
}

// round 13
// speedup vs baseline: 1.2201x; 1.0860x over previous
#include <cuda_runtime.h>
#include <math.h>
#include <stdint.h>

// ---------------- problem constants ----------------
#define T_SEQ   2048
#define C_DIM   2048
#define NH      16
#define HS      128
#define NLQ     1536
#define NLKV    512
#define DHR     64
#define DQK     (NLKV + DHR)   // 576
#define HALF_R  (DHR/2)        // 32
#define CKW     (NLQ + DQK)    // 2112: [c_q | Kc] combined width
#define QOW     (C_DIM + NH*DHR) // 3072: [q_all | qr_all] combined width

// ---------------- scratch (device globals; no allocation allowed) ----------------
__device__ float g_ck  [(size_t)T_SEQ * CKW];          // [c_q (0:1536) | Kc (1536:2112)]
__device__ float g_qout[(size_t)T_SEQ * QOW];          // [q_all (0:2048) | qr (2048:3072)]
__device__ float g_skp [2 * (size_t)NLKV * C_DIM];     // Veff split-K partials
__device__ float g_Qc  [(size_t)NH * T_SEQ * DQK];
__device__ float g_S   [(size_t)NH * T_SEQ * T_SEQ];
__device__ float g_ylat[(size_t)NH * T_SEQ * NLKV];
__device__ float g_WuvT[(size_t)NLKV * C_DIM];
__device__ float g_Veff[(size_t)NLKV * C_DIM];
// tf32-rounded weights
__device__ float g_rx   [(size_t)T_SEQ * C_DIM];
__device__ float g_rWp1 [(size_t)CKW * C_DIM];         // [W_dq; W_dkv; W_kr] (2112x2048)
__device__ float g_rWq  [(size_t)NLQ * QOW];           // [M_uq | W_qr^T]    (1536x3072)
__device__ float g_rWuk [(size_t)C_DIM * NLKV];
__device__ float g_rWo  [(size_t)C_DIM * C_DIM];

// ---------------- tf32 helpers ----------------
__device__ __forceinline__ uint32_t f2tf(float f)
{
    uint32_t r;
    asm("cvt.rna.tf32.f32 %0, %1;" : "=r"(r) : "f"(f));
    return r;
}
__device__ __forceinline__ float roundtf(float f) { return __uint_as_float(f2tf(f)); }

__device__ __forceinline__ void mma_tf32(float* d, const uint32_t* a, const uint32_t* b)
{
    asm volatile(
        "mma.sync.aligned.m16n8k8.row.col.f32.tf32.tf32.f32 "
        "{%0,%1,%2,%3},{%4,%5,%6,%7},{%8,%9},{%0,%1,%2,%3};"
        : "+f"(d[0]), "+f"(d[1]), "+f"(d[2]), "+f"(d[3])
        : "r"(a[0]), "r"(a[1]), "r"(a[2]), "r"(a[3]),
          "r"(b[0]), "r"(b[1]));
}

__device__ __forceinline__ void cp16(uint32_t dst, const void* src, bool pred)
{
    int sz = pred ? 16 : 0;
    asm volatile("cp.async.cg.shared.global [%0], [%1], 16, %2;"
                 :: "r"(dst), "l"(src), "r"(sz));
}
__device__ __forceinline__ uint32_t smaddr(const void* p)
{
    return (uint32_t)__cvta_generic_to_shared(p);
}

// ---------------- tensor-core GEMM: cp.async 4-stage pipeline (R8 engine, verbatim) ----------------
// CTA 128x128, 256 threads / 8 warps, warp tile 64x32.
// Operands MUST be tf32-pre-rounded fp32 in gmem.
// C[m,n] = alpha * sum_k A[m,k]*B(k,n); B: BT ? B[n*ldb+k] : B[k*ldb+n].
// CMODE: 0 plain; 1 causal CTA-tile skip; 2 causal K-limit (kEnd=m0+BM).
// RND: round stored result to tf32.
// Invariants: M%128==0, kEnd%16==0, N%4==0, rows 16B-aligned.
#define BM 128
#define BN 128
#define BK 16
#define STAGE_W 5120
#define SMEM_BYTES (4 * STAGE_W * 4)

template<bool BT, int CMODE, bool RND>
__global__ __launch_bounds__(256, 2)
void gemm_tc(int M, int N, int K,
             const float* __restrict__ A, int lda, long long sA,
             const float* __restrict__ B, int ldb, long long sB,
             float* __restrict__ C, int ldc, long long sC,
             float alpha)
{
    const int m0 = blockIdx.y * BM;
    const int n0 = blockIdx.x * BN;
    if (CMODE == 1 && n0 > m0) return;
    int kEnd = K;
    if (CMODE == 2) kEnd = min(K, m0 + BM);

    const long long z = blockIdx.z;
    A += z * sA;  B += z * sB;  C += z * sC;

    extern __shared__ uint32_t dsm[];

    const int tid  = threadIdx.x;
    const int lane = tid & 31;
    const int w    = tid >> 5;
    const int gid  = lane >> 2;   // 0..7
    const int tg   = lane & 3;    // 0..3
    const int mBase = (w >> 2) * 64;
    const int nBase = (w & 3) * 32;

    const int aRow = tid >> 1;            // 0..127
    const int aJ   = (tid & 1) * 8;       // 0 or 8
    const int bK   = tid >> 5;            // 0..7 (NN)
    const int bN4  = (tid & 31) * 4;      // 0..124 (NN)

    float acc[4][4][4];
#pragma unroll
    for (int i = 0; i < 4; i++)
#pragma unroll
        for (int j = 0; j < 4; j++)
#pragma unroll
            for (int r = 0; r < 4; r++) acc[i][j][r] = 0.f;

    auto cp_tile = [&](int s, int k0) {
        uint32_t* as = dsm + s * STAGE_W;
        uint32_t* bs = as + 2560;
        const float* pA = A + (long long)(m0 + aRow) * lda + k0 + aJ;
        cp16(smaddr(&as[aRow * 20 + aJ]),     pA,     true);
        cp16(smaddr(&as[aRow * 20 + aJ + 4]), pA + 4, true);
        if (BT) {
            const int gn = n0 + aRow;
            const bool p = gn < N;
            const float* pB = B + (long long)(p ? gn : 0) * ldb + k0 + aJ;
            cp16(smaddr(&bs[aRow * 20 + aJ]),     pB,     p);
            cp16(smaddr(&bs[aRow * 20 + aJ + 4]), pB + 4, p);
        } else {
            const int gn = n0 + bN4;
            const bool p = gn < N;
            const int gc = p ? gn : 0;
            cp16(smaddr(&bs[bK * 136 + bN4]),       B + (long long)(k0 + bK) * ldb + gc,     p);
            cp16(smaddr(&bs[(bK + 8) * 136 + bN4]), B + (long long)(k0 + bK + 8) * ldb + gc, p);
        }
    };

    auto compute = [&](int s) {
        const uint32_t* as = dsm + s * STAGE_W;
        const uint32_t* bs = as + 2560;
#pragma unroll
        for (int kk = 0; kk < BK; kk += 8) {
            uint32_t af[4][4], bf[4][2];
#pragma unroll
            for (int mt = 0; mt < 4; mt++) {
                const int r = mBase + mt * 16;
                af[mt][0] = as[(r + gid) * 20 + kk + tg];
                af[mt][1] = as[(r + gid + 8) * 20 + kk + tg];
                af[mt][2] = as[(r + gid) * 20 + kk + tg + 4];
                af[mt][3] = as[(r + gid + 8) * 20 + kk + tg + 4];
            }
#pragma unroll
            for (int nt = 0; nt < 4; nt++) {
                const int c = nBase + nt * 8 + gid;
                if (BT) {
                    bf[nt][0] = bs[c * 20 + kk + tg];
                    bf[nt][1] = bs[c * 20 + kk + tg + 4];
                } else {
                    bf[nt][0] = bs[(kk + tg) * 136 + c];
                    bf[nt][1] = bs[(kk + tg + 4) * 136 + c];
                }
            }
#pragma unroll
            for (int mt = 0; mt < 4; mt++)
#pragma unroll
                for (int nt = 0; nt < 4; nt++)
                    mma_tf32(acc[mt][nt], af[mt], bf[nt]);
        }
    };

    const int ntiles = kEnd / BK;

#pragma unroll
    for (int s = 0; s < 3; s++) {
        if (s < ntiles) cp_tile(s, s * BK);
        asm volatile("cp.async.commit_group;");
    }

    for (int kt = 0; kt < ntiles; kt++) {
        asm volatile("cp.async.wait_group 2;");
        __syncthreads();
        const int tn = kt + 3;
        if (tn < ntiles) cp_tile(tn & 3, tn * BK);
        asm volatile("cp.async.commit_group;");
        compute(kt & 3);
    }
    asm volatile("cp.async.wait_all;");

#pragma unroll
    for (int mt = 0; mt < 4; mt++) {
        const int r = m0 + mBase + mt * 16 + gid;
#pragma unroll
        for (int nt = 0; nt < 4; nt++) {
            const int c = n0 + nBase + nt * 8 + 2 * tg;
            if (c < N) {
                float2 v0, v1;
                if (RND) {
                    v0.x = roundtf(acc[mt][nt][0] * alpha);
                    v0.y = roundtf(acc[mt][nt][1] * alpha);
                    v1.x = roundtf(acc[mt][nt][2] * alpha);
                    v1.y = roundtf(acc[mt][nt][3] * alpha);
                } else {
                    v0.x = acc[mt][nt][0] * alpha;
                    v0.y = acc[mt][nt][1] * alpha;
                    v1.x = acc[mt][nt][2] * alpha;
                    v1.y = acc[mt][nt][3] * alpha;
                }
                *reinterpret_cast<float2*>(C + (long long)r * ldc + c)       = v0;
                *reinterpret_cast<float2*>(C + (long long)(r + 8) * ldc + c) = v1;
            }
        }
    }
}

// ---------------- tf32 round-copy (vectorized) ----------------
__global__ void round_copy4(const float4* __restrict__ src, float4* __restrict__ dst, int n4)
{
    int i = blockIdx.x * blockDim.x + threadIdx.x;
    if (i < n4) {
        float4 v = src[i];
        v.x = roundtf(v.x); v.y = roundtf(v.y); v.z = roundtf(v.z); v.w = roundtf(v.w);
        dst[i] = v;
    }
}

// ---------------- pack [M_uq | W_qr^T] -> g_rWq (1536 x 3072, rounded) ----------------
__global__ void pack_uqqr_kernel(const float* __restrict__ Wuq, const float* __restrict__ Wqr,
                                 float* __restrict__ dst)
{
    int idx = blockIdx.x * blockDim.x + threadIdx.x;
    const int total = NLQ * QOW;
    if (idx < total) {
        int r = idx / QOW, c = idx % QOW;
        float v = (c < C_DIM) ? Wuq[(long long)r * C_DIM + c]
                              : Wqr[(long long)(c - C_DIM) * NLQ + r];
        dst[idx] = roundtf(v);
    }
}

// ---------------- W_uv transpose (rounded): (2048x512) -> (512x2048) ----------------
__global__ void transpose_wuv_kernel(const float* __restrict__ W, float* __restrict__ Wt)
{
    int idx = blockIdx.x * blockDim.x + threadIdx.x;
    if (idx < C_DIM * NLKV) {
        int k = idx % NLKV;
        int c = idx / NLKV;
        Wt[(long long)k * C_DIM + c] = roundtf(W[idx]);
    }
}

// ---------------- 2-way split-K reduce, rounded ----------------
__global__ void reduce2_kernel(const float* __restrict__ p, float* __restrict__ dst,
                               int n, long long sp)
{
    int i = blockIdx.x * blockDim.x + threadIdx.x;
    if (i < n) dst[i] = roundtf(p[i] + p[sp + i]);
}

// ---------------- RoPE: Q from g_qout cols 2048:3072; K in place on g_ck cols 2048:2112 ----------------
__global__ void rope_kernel(const float* __restrict__ qr, int qld,
                            float* __restrict__ Kc, int kld,
                            const float* __restrict__ cosT, const float* __restrict__ sinT,
                            float* __restrict__ Qc)
{
    int idx = blockIdx.x * blockDim.x + threadIdx.x;
    const int totalQ = T_SEQ * NH * HALF_R;
    if (idx < totalQ) {
        int j = idx % HALF_R;
        int h = (idx / HALF_R) % NH;
        int t = idx / (HALF_R * NH);
        const float* src = qr + (long long)t * qld + h * DHR;
        float re = src[2 * j];
        float im = src[2 * j + 1];
        float c = cosT[t * HALF_R + j];
        float s = sinT[t * HALF_R + j];
        float* dst = Qc + ((long long)h * T_SEQ + t) * DQK + NLKV;
        dst[2 * j]     = roundtf(re * c - im * s);
        dst[2 * j + 1] = roundtf(re * s + im * c);
    } else {
        int k = idx - totalQ;
        if (k < T_SEQ * HALF_R) {
            int j = k % HALF_R;
            int t = k / HALF_R;
            float* kp = Kc + (long long)t * kld + NLKV;
            float re = kp[2 * j];
            float im = kp[2 * j + 1];
            float c = cosT[t * HALF_R + j];
            float s = sinT[t * HALF_R + j];
            kp[2 * j]     = roundtf(re * c - im * s);
            kp[2 * j + 1] = roundtf(re * s + im * c);
        }
    }
}

// ---------------- causal softmax: register-cached exp, 2R+1W, trimmed zero-fill ----------------
__global__ __launch_bounds__(256)
void softmax_kernel(float* __restrict__ S)
{
    const int t = blockIdx.x;
    float* row = S + ((long long)blockIdx.y * T_SEQ + t) * (long long)T_SEQ;
    const int len = t + 1;
    const int tid = threadIdx.x;
    __shared__ float sm[32];

    // --- max ---
    float m = -3.4e38f;
#pragma unroll
    for (int u = 0; u < 8; u++) {
        int i = tid + u * 256;
        if (i < len) m = fmaxf(m, row[i]);
    }
#pragma unroll
    for (int o = 16; o; o >>= 1) m = fmaxf(m, __shfl_xor_sync(0xffffffffu, m, o));
    if ((tid & 31) == 0) sm[tid >> 5] = m;
    __syncthreads();
    if (tid < 32) {
        float v = (tid < 8) ? sm[tid] : -3.4e38f;
#pragma unroll
        for (int o = 4; o; o >>= 1) v = fmaxf(v, __shfl_xor_sync(0xffffffffu, v, o));
        if (tid == 0) sm[0] = v;
    }
    __syncthreads();
    m = sm[0];
    __syncthreads();

    // --- exp (cached in regs) + sum ---
    float ev[8];
    float s = 0.f;
#pragma unroll
    for (int u = 0; u < 8; u++) {
        int i = tid + u * 256;
        float e = (i < len) ? __expf(row[i] - m) : 0.f;
        ev[u] = e;
        s += e;
    }
#pragma unroll
    for (int o = 16; o; o >>= 1) s += __shfl_xor_sync(0xffffffffu, s, o);
    if ((tid & 31) == 0) sm[tid >> 5] = s;
    __syncthreads();
    if (tid < 32) {
        float v = (tid < 8) ? sm[tid] : 0.f;
#pragma unroll
        for (int o = 4; o; o >>= 1) v += __shfl_xor_sync(0xffffffffu, v, o);
        if (tid == 0) sm[0] = v;
    }
    __syncthreads();
    const float inv = 1.f / sm[0];

    // --- single write pass ---
#pragma unroll
    for (int u = 0; u < 8; u++) {
        int i = tid + u * 256;
        if (i < len) row[i] = roundtf(ev[u] * inv);
    }
    const int fillEnd = min(T_SEQ, (len + 127) & ~127);   // PV reads only this window
    for (int i = len + tid; i < fillEnd; i += 256) row[i] = 0.f;
}

// ---------------- host orchestration ----------------
static inline dim3 gemm_grid(int M, int N, int Z)
{
    return dim3((N + BN - 1) / BN, (M + BM - 1) / BM, Z);
}

static void rcopy(const float* src, float* dst, int n)
{
    int n4 = n / 4;
    round_copy4<<<(n4 + 255) / 256, 256>>>((const float4*)src, (float4*)dst, n4);
}

extern "C" void kernel_launch(void* const* d_in, const int* in_sizes, int n_in,
                              void* d_out, int out_size)
{
    const float* x     = (const float*)d_in[0];
    const float* fcos  = (const float*)d_in[1];
    const float* fsin  = (const float*)d_in[2];
    const float* W_dq  = (const float*)d_in[3];
    const float* W_uq  = (const float*)d_in[4];
    const float* W_dkv = (const float*)d_in[5];
    const float* W_uk  = (const float*)d_in[6];
    const float* W_uv  = (const float*)d_in[7];
    const float* W_qr  = (const float*)d_in[8];
    const float* W_kr  = (const float*)d_in[9];
    const float* W_o   = (const float*)d_in[10];
    float* out = (float*)d_out;

    float *p_ck, *p_qout, *p_skp, *p_Qc, *p_S, *p_ylat, *p_WuvT, *p_Veff;
    float *p_rx, *p_rWp1, *p_rWq, *p_rWuk, *p_rWo;
    cudaGetSymbolAddress((void**)&p_ck,   g_ck);
    cudaGetSymbolAddress((void**)&p_qout, g_qout);
    cudaGetSymbolAddress((void**)&p_skp,  g_skp);
    cudaGetSymbolAddress((void**)&p_Qc,   g_Qc);
    cudaGetSymbolAddress((void**)&p_S,    g_S);
    cudaGetSymbolAddress((void**)&p_ylat, g_ylat);
    cudaGetSymbolAddress((void**)&p_WuvT, g_WuvT);
    cudaGetSymbolAddress((void**)&p_Veff, g_Veff);
    cudaGetSymbolAddress((void**)&p_rx,   g_rx);
    cudaGetSymbolAddress((void**)&p_rWp1, g_rWp1);
    cudaGetSymbolAddress((void**)&p_rWq,  g_rWq);
    cudaGetSymbolAddress((void**)&p_rWuk, g_rWuk);
    cudaGetSymbolAddress((void**)&p_rWo,  g_rWo);

    cudaFuncSetAttribute(gemm_tc<true, 0, true>,  cudaFuncAttributeMaxDynamicSharedMemorySize, SMEM_BYTES);
    cudaFuncSetAttribute(gemm_tc<true, 0, false>, cudaFuncAttributeMaxDynamicSharedMemorySize, SMEM_BYTES);
    cudaFuncSetAttribute(gemm_tc<true, 1, false>, cudaFuncAttributeMaxDynamicSharedMemorySize, SMEM_BYTES);
    cudaFuncSetAttribute(gemm_tc<false, 0, true>, cudaFuncAttributeMaxDynamicSharedMemorySize, SMEM_BYTES);
    cudaFuncSetAttribute(gemm_tc<false, 0, false>,cudaFuncAttributeMaxDynamicSharedMemorySize, SMEM_BYTES);
    cudaFuncSetAttribute(gemm_tc<false, 2, true>, cudaFuncAttributeMaxDynamicSharedMemorySize, SMEM_BYTES);

    const float scale = 1.0f / sqrtf((float)(HS + DHR));
    const dim3 blk(256);

    // 0) rounded weights
    rcopy(x,     p_rx,   T_SEQ * C_DIM);
    rcopy(W_dq,  p_rWp1,                              NLQ * C_DIM);      // rows 0:1536
    rcopy(W_dkv, p_rWp1 + (size_t)NLQ * C_DIM,        NLKV * C_DIM);     // rows 1536:2048
    rcopy(W_kr,  p_rWp1 + (size_t)(NLQ+NLKV) * C_DIM, DHR * C_DIM);      // rows 2048:2112
    pack_uqqr_kernel<<<(NLQ * QOW + 255) / 256, blk>>>(W_uq, W_qr, p_rWq);
    rcopy(W_uk,  p_rWuk, C_DIM * NLKV);
    rcopy(W_o,   p_rWo,  C_DIM * C_DIM);
    transpose_wuv_kernel<<<(C_DIM * NLKV + 255) / 256, blk>>>(W_uv, p_WuvT);

    // 1) [c_q | Kc] = x @ [W_dq;W_dkv;W_kr]^T   (2048x2112, K=2048)  NT, rounded
    gemm_tc<true, 0, true><<<gemm_grid(T_SEQ, CKW, 1), blk, SMEM_BYTES>>>(
        T_SEQ, CKW, C_DIM, p_rx, C_DIM, 0, p_rWp1, C_DIM, 0, p_ck, CKW, 0, 1.f);

    // 2) Veff = WuvT @ W_o^T    split-K x2 -> 128 CTAs + rounded reduce
    gemm_tc<true, 0, false><<<dim3(16, 4, 2), blk, SMEM_BYTES>>>(
        NLKV, C_DIM, 1024,
        p_WuvT, C_DIM, 1024LL,
        p_rWo,  C_DIM, 1024LL,
        p_skp,  C_DIM, (long long)NLKV * C_DIM, 1.f);
    reduce2_kernel<<<(NLKV * C_DIM + 255) / 256, blk>>>(
        p_skp, p_Veff, NLKV * C_DIM, (long long)NLKV * C_DIM);

    // 3) [q_all | qr] = c_q @ [M_uq | W_qr^T]   (2048x3072, K=1536)  NN, rounded
    gemm_tc<false, 0, true><<<gemm_grid(T_SEQ, QOW, 1), blk, SMEM_BYTES>>>(
        T_SEQ, QOW, NLQ, p_ck, CKW, 0, p_rWq, QOW, 0, p_qout, QOW, 0, 1.f);

    // 4) Qc[h][:, 0:512] = q_all[:, h*128:] @ W_uk[h*128:, :]   batched NN, rounded
    gemm_tc<false, 0, true><<<gemm_grid(T_SEQ, NLKV, NH), blk, SMEM_BYTES>>>(
        T_SEQ, NLKV, HS,
        p_qout, QOW,  (long long)HS,
        p_rWuk, NLKV, (long long)HS * NLKV,
        p_Qc,   DQK,  (long long)T_SEQ * DQK, 1.f);

    // 5) RoPE: Qc[...,512:576] from qout cols 2048:3072; Kc cols 512:576 in place
    {
        int total = T_SEQ * NH * HALF_R + T_SEQ * HALF_R;
        rope_kernel<<<(total + 255) / 256, blk>>>(
            p_qout + C_DIM, QOW, p_ck + NLQ, CKW, fcos, fsin, p_Qc);
    }

    // 6) S[h] = scale * Qc[h] @ Kc^T   (2048x2048, K=576) batched NT, causal skip
    gemm_tc<true, 1, false><<<gemm_grid(T_SEQ, T_SEQ, NH), blk, SMEM_BYTES>>>(
        T_SEQ, T_SEQ, DQK,
        p_Qc,        DQK, (long long)T_SEQ * DQK,
        p_ck + NLQ,  CKW, 0LL,
        p_S,  T_SEQ, (long long)T_SEQ * T_SEQ, scale);

    // 7) causal softmax
    softmax_kernel<<<dim3(T_SEQ, NH), blk>>>(p_S);

    // 8) y_lat[h] = P[h] @ Kc[:, 0:512]   batched NN, K-limited, rounded
    gemm_tc<false, 2, true><<<gemm_grid(T_SEQ, NLKV, NH), blk, SMEM_BYTES>>>(
        T_SEQ, NLKV, T_SEQ,
        p_S,        T_SEQ, (long long)T_SEQ * T_SEQ,
        p_ck + NLQ, CKW,   0LL,
        p_ylat, NLKV, (long long)T_SEQ * NLKV, 1.f);

    // 9) out[:, h*128:(h+1)*128] = y_lat[h] @ Veff[:, h*128:]  batched NN
    gemm_tc<false, 0, false><<<gemm_grid(T_SEQ, HS, NH), blk, SMEM_BYTES>>>(
        T_SEQ, HS, NLKV,
        p_ylat, NLKV,  (long long)T_SEQ * NLKV,
        p_Veff, C_DIM, (long long)HS,
        out,    C_DIM, (long long)HS, 1.f);
}